// round 16
// baseline (speedup 1.0000x reference)
#include <cuda_runtime.h>
#include <stdint.h>

#define N_NODES 10000
#define N_EDGES 320000
#define N_PAIRS 2048
#define IN_CH   128
#define HIDDEN  512

#define ROW_WB  320
#define ROW_B4  80
#define BMP_U4  ((size_t)N_NODES * ROW_WB / 4)   // 800000 uint4

#define HSIZE   32768
#define HMASK   (HSIZE - 1)

#define SCATTER_BLOCKS 2500          // 640000 directed edges / 256
#define PREP_BLOCKS    256           // W1 duplication: 512 weights per block

__device__ __align__(16) unsigned int g_B[(size_t)N_NODES * ROW_WB];
__device__ __align__(16) unsigned int g_hk[HSIZE];
__device__ __align__(16) unsigned int g_hc[HSIZE];
__device__ __align__(16) float g_XS[N_PAIRS * 2 * IN_CH];
__device__ __align__(16) unsigned char g_F[N_NODES];
// W1 with each weight duplicated into both f32x2 lanes: [256][512] float2
__device__ __align__(16) float2 g_W1d[2 * IN_CH * HIDDEN];

// ---------------------------------------------------------------------------
__device__ __forceinline__ int detect64(const void* p) {
    const unsigned int* p32 = (const unsigned int*)p;
    int lane = threadIdx.x & 31;
    bool all0 = (p32[2 * lane + 1] | p32[2 * (lane + 32) + 1]) == 0u;
    return __ballot_sync(0xFFFFFFFFu, all0) == 0xFFFFFFFFu;
}
__device__ __forceinline__ long long load_idx(const void* p, int is64, long long j) {
    if (is64) return ((const long long*)p)[j];
    return (long long)((const int*)p)[j];
}

__device__ __forceinline__ void hash_add(unsigned key) {
    unsigned idx = (key * 2654435761u) & HMASK;
    for (;;) {
        unsigned cur = g_hk[idx];
        if (cur == key + 1u) { atomicAdd(&g_hc[idx], 1u); return; }
        if (cur == 0u) {
            unsigned old = atomicCAS(&g_hk[idx], 0u, key + 1u);
            if (old == 0u || old == key + 1u) { atomicAdd(&g_hc[idx], 1u); return; }
        }
        idx = (idx + 1u) & HMASK;
    }
}
__device__ __forceinline__ unsigned hash_get(unsigned key) {
    unsigned idx = (key * 2654435761u) & HMASK;
    for (;;) {
        unsigned cur = g_hk[idx];
        if (cur == 0u) return 0u;
        if (cur == key + 1u) return g_hc[idx];
        idx = (idx + 1u) & HMASK;
    }
}

// ---------------------------------------------------------------------------
// 0) Flag target nodes (idempotent across replays)
// ---------------------------------------------------------------------------
__global__ void flag_kernel(const void* __restrict__ tar) {
    int is64 = detect64(tar);
    int t = blockIdx.x * blockDim.x + threadIdx.x;
    if (t >= 2 * N_PAIRS) return;
    long long n = load_idx(tar, is64, t);
    g_F[n] = 1;
}

// ---------------------------------------------------------------------------
// 1) Scatter (blocks < SCATTER_BLOCKS) + W1 duplication (trailing blocks).
//    The copy rides in scatter's idle issue slots (scatter is atomic-bound).
// ---------------------------------------------------------------------------
__global__ void scatter_kernel(const void* __restrict__ ei,
                               const float* __restrict__ W1) {
    if (blockIdx.x >= SCATTER_BLOCKS) {
        int w = (blockIdx.x - SCATTER_BLOCKS) * 512 + threadIdx.x;
#pragma unroll
        for (int l = 0; l < 2; l++, w += 256) {
            float v = W1[w];
            g_W1d[w] = make_float2(v, v);
        }
        return;
    }

    int is64 = detect64(ei);
    int t = blockIdx.x * blockDim.x + threadIdx.x;

    int e   = (t < N_EDGES) ? t : t - N_EDGES;
    int rev = (t >= N_EDGES);

    long long a = load_idx(ei, is64, e);
    long long b = load_idx(ei, is64, (long long)N_EDGES + e);
    long long s = rev ? b : a;
    long long d = rev ? a : b;

    if (!g_F[s]) return;   // row never read by pairs -> skip

    unsigned bd = 1u << (d & 31);
    unsigned old = atomicOr(&g_B[(size_t)s * ROW_WB + (size_t)(d >> 5)], bd);
    if (old & bd) hash_add((unsigned)(s * 16384 + d));
}

// ---------------------------------------------------------------------------
// 2) Pairs: intersect rows, build xs, init out[b] = b2[0]
// ---------------------------------------------------------------------------
__global__ void pairs_kernel(const void* __restrict__ tar,
                             const float* __restrict__ x,
                             const float* __restrict__ b2,
                             float* __restrict__ out) {
    __shared__ int   s_n[512];
    __shared__ float s_w[512];
    __shared__ int   s_cnt;

    int is64 = detect64(tar);
    int b   = blockIdx.x;
    int tid = threadIdx.x;
    if (tid == 0) {
        s_cnt = 0;
        out[b] = b2[0];
    }
    __syncthreads();

    long long ti = load_idx(tar, is64, b);
    long long tj = load_idx(tar, is64, (long long)N_PAIRS + b);

    if (tid < ROW_B4) {
        const uint4* rowi = reinterpret_cast<const uint4*>(&g_B[(size_t)ti * ROW_WB]);
        const uint4* rowj = reinterpret_cast<const uint4*>(&g_B[(size_t)tj * ROW_WB]);
        uint4 a = rowi[tid];
        uint4 q = rowj[tid];
        unsigned int m4[4] = {a.x & q.x, a.y & q.y, a.z & q.z, a.w & q.w};
#pragma unroll
        for (int w = 0; w < 4; w++) {
            unsigned int m = m4[w];
            while (m) {
                int bit = __ffs(m) - 1;
                int n = tid * 128 + w * 32 + bit;
                unsigned ua = 1u + hash_get((unsigned)(ti * 16384 + n));
                unsigned ub = 1u + hash_get((unsigned)(tj * 16384 + n));
                int idx = atomicAdd(&s_cnt, 1);
                if (idx < 512) {
                    s_n[idx] = n;
                    s_w[idx] = (float)(ua * ub);
                }
                m &= m - 1;
            }
        }
    }
    __syncthreads();

    int cnt = s_cnt < 512 ? s_cnt : 512;

    float xi = x[(size_t)ti * IN_CH + tid];
    float xj = x[(size_t)tj * IN_CH + tid];

    float acc = 0.f;
    for (int e = 0; e < cnt; e++)
        acc = fmaf(s_w[e], x[(size_t)s_n[e] * IN_CH + tid], acc);

    g_XS[(size_t)b * (2 * IN_CH) + tid]         = xi * xj;
    g_XS[(size_t)b * (2 * IN_CH) + IN_CH + tid] = acc;
}

// ---------------------------------------------------------------------------
// 3) Fused GEMM (v2 tiles) with pre-duplicated weights: per k the hot loop is
//    16 FFMA2 + 4 LDS.128 (no dup movs). + atomicAdd epilogue + clear tail.
// ---------------------------------------------------------------------------
#define BM 128
#define BN 64
#define BK 32
#define KTOT (2 * IN_CH)
#define NTILES (KTOT / BK)   // 8

__device__ __forceinline__ unsigned long long fma2(
    unsigned long long a, unsigned long long b, unsigned long long c) {
    unsigned long long d;
    asm("fma.rn.f32x2 %0, %1, %2, %3;" : "=l"(d) : "l"(a), "l"(b), "l"(c));
    return d;
}

__global__ __launch_bounds__(256, 1)
void mlp_kernel(const float* __restrict__ b1,
                const float* __restrict__ W2, float* __restrict__ out) {
    __shared__ __align__(16) float s_x[BK][BM + 4];     // 16.9 KB
    __shared__ __align__(16) float s_wd[BK][2 * BN];    // 16 KB (duplicated)
    __shared__ float s_red[BM][17];                     // 8.7 KB

    int tid = threadIdx.x;
    int tx  = tid & 15;
    int ty  = tid >> 4;
    int b0  = (blockIdx.x & 15) * BM;
    int h0  = (blockIdx.x >> 4) * BN;

    float4 xr[4];
    float4 wr[4];
#pragma unroll
    for (int l = 0; l < 4; l++) {
        int fi = tid + l * 256;
        int p  = fi >> 3;
        int kc = fi & 7;
        xr[l] = *reinterpret_cast<const float4*>(&g_XS[(size_t)(b0 + p) * KTOT + kc * 4]);
    }
#pragma unroll
    for (int l = 0; l < 4; l++) {
        int fi = tid + l * 256;          // float4 index in 32 x (64 dup-pairs)
        int kk = fi >> 5;                // 32 float4 per k-row
        int cc = fi & 31;                // float4 col = 2 dup-weights
        wr[l] = *reinterpret_cast<const float4*>(
            &g_W1d[(size_t)kk * HIDDEN + h0 + cc * 2]);
    }

    unsigned long long acc2[4][4];
#pragma unroll
    for (int i = 0; i < 4; i++)
#pragma unroll
        for (int j = 0; j < 4; j++) acc2[i][j] = 0ull;

    for (int t = 0; t < NTILES; t++) {
#pragma unroll
        for (int l = 0; l < 4; l++) {
            int fi = tid + l * 256;
            int p  = fi >> 3;
            int kc = fi & 7;
            s_x[kc * 4 + 0][p] = xr[l].x;
            s_x[kc * 4 + 1][p] = xr[l].y;
            s_x[kc * 4 + 2][p] = xr[l].z;
            s_x[kc * 4 + 3][p] = xr[l].w;
        }
#pragma unroll
        for (int l = 0; l < 4; l++) {
            int fi = tid + l * 256;
            int kk = fi >> 5;
            int cc = fi & 31;
            *reinterpret_cast<float4*>(&s_wd[kk][cc * 4]) = wr[l];
        }
        __syncthreads();

        if (t + 1 < NTILES) {
            int k0 = (t + 1) * BK;
#pragma unroll
            for (int l = 0; l < 4; l++) {
                int fi = tid + l * 256;
                int p  = fi >> 3;
                int kc = fi & 7;
                xr[l] = *reinterpret_cast<const float4*>(
                    &g_XS[(size_t)(b0 + p) * KTOT + k0 + kc * 4]);
            }
#pragma unroll
            for (int l = 0; l < 4; l++) {
                int fi = tid + l * 256;
                int kk = fi >> 5;
                int cc = fi & 31;
                wr[l] = *reinterpret_cast<const float4*>(
                    &g_W1d[(size_t)(k0 + kk) * HIDDEN + h0 + cc * 2]);
            }
        }

#pragma unroll 8
        for (int k = 0; k < BK; k++) {
            ulonglong2 wa = *reinterpret_cast<const ulonglong2*>(&s_wd[k][tx * 8]);
            ulonglong2 wb = *reinterpret_cast<const ulonglong2*>(&s_wd[k][tx * 8 + 4]);
            unsigned long long wd[4] = {wa.x, wa.y, wb.x, wb.y};
            ulonglong2 xa = *reinterpret_cast<const ulonglong2*>(&s_x[k][ty * 8]);
            ulonglong2 xb = *reinterpret_cast<const ulonglong2*>(&s_x[k][ty * 8 + 4]);
            unsigned long long xp[4] = {xa.x, xa.y, xb.x, xb.y};
#pragma unroll
            for (int pp = 0; pp < 4; pp++)
#pragma unroll
                for (int hh = 0; hh < 4; hh++)
                    acc2[pp][hh] = fma2(xp[pp], wd[hh], acc2[pp][hh]);
        }
        __syncthreads();
    }

    float4 b1v = *reinterpret_cast<const float4*>(&b1[h0 + tx * 4]);
    float4 w2v = *reinterpret_cast<const float4*>(&W2[h0 + tx * 4]);
    float bb[4] = {b1v.x, b1v.y, b1v.z, b1v.w};
    float ww[4] = {w2v.x, w2v.y, w2v.z, w2v.w};

    float pval[8];
#pragma unroll
    for (int pp = 0; pp < 4; pp++) {
        float lo = 0.f, hi = 0.f;
#pragma unroll
        for (int hh = 0; hh < 4; hh++) {
            union { unsigned long long u; float2 f; } cv;
            cv.u = acc2[pp][hh];
            lo += fmaxf(cv.f.x + bb[hh], 0.f) * ww[hh];
            hi += fmaxf(cv.f.y + bb[hh], 0.f) * ww[hh];
        }
        pval[pp * 2 + 0] = lo;
        pval[pp * 2 + 1] = hi;
    }

#pragma unroll
    for (int q = 0; q < 8; q++)
        s_red[ty * 8 + q][tx] = pval[q];
    __syncthreads();

    if (tid < BM) {
        float s = 0.f;
#pragma unroll
        for (int t = 0; t < 16; t++) s += s_red[tid][t];
        atomicAdd(&out[b0 + tid], s);
    }

    // -------- clear tail: this block zeroes its 1/128 slice of bitmap + hash
    {
        uint4 z = make_uint4(0u, 0u, 0u, 0u);
        uint4* bp = reinterpret_cast<uint4*>(g_B);
        size_t start = (size_t)blockIdx.x * (BMP_U4 / 128);
        size_t end   = start + (BMP_U4 / 128);
        for (size_t w = start + tid; w < end; w += 256)
            bp[w] = z;

        int hs = blockIdx.x * (HSIZE / 4 / 128);
        if (tid < HSIZE / 4 / 128) {
            reinterpret_cast<uint4*>(g_hk)[hs + tid] = z;
            reinterpret_cast<uint4*>(g_hc)[hs + tid] = z;
        }
    }
}

// ---------------------------------------------------------------------------
// launch (single stream, serial, 4 kernels)
// ---------------------------------------------------------------------------
extern "C" void kernel_launch(void* const* d_in, const int* in_sizes, int n_in,
                              void* d_out, int out_size) {
    const float* x   = (const float*)d_in[0];
    const void*  ei  = d_in[1];
    const void*  tar = d_in[2];
    const float* W1  = (const float*)d_in[3];
    const float* b1  = (const float*)d_in[4];
    const float* W2  = (const float*)d_in[5];
    const float* b2  = (const float*)d_in[6];
    float*       out = (float*)d_out;

    (void)in_sizes; (void)n_in; (void)out_size;

    flag_kernel<<<(2 * N_PAIRS + 255) / 256, 256>>>(tar);
    scatter_kernel<<<SCATTER_BLOCKS + PREP_BLOCKS, 256>>>(ei, W1);
    pairs_kernel<<<N_PAIRS, 128>>>(tar, x, b2, out);
    mlp_kernel<<<128, 256>>>(b1, W2, out);
}

// round 17
// speedup vs baseline: 1.3080x; 1.3080x over previous
#include <cuda_runtime.h>
#include <stdint.h>

#define N_NODES 10000
#define N_EDGES 320000
#define N_PAIRS 2048
#define IN_CH   128
#define HIDDEN  512

#define ROW_WB  320
#define ROW_B4  80
#define BMP_U4  ((size_t)N_NODES * ROW_WB / 4)   // 800000 uint4

#define HSIZE   32768
#define HMASK   (HSIZE - 1)

__device__ __align__(16) unsigned int g_B[(size_t)N_NODES * ROW_WB];
__device__ __align__(16) unsigned int g_hk[HSIZE];
__device__ __align__(16) unsigned int g_hc[HSIZE];
__device__ __align__(16) float g_XS[N_PAIRS * 2 * IN_CH];
__device__ __align__(16) unsigned char g_F[N_NODES];

// ---------------------------------------------------------------------------
__device__ __forceinline__ int detect64(const void* p) {
    const unsigned int* p32 = (const unsigned int*)p;
    int lane = threadIdx.x & 31;
    bool all0 = (p32[2 * lane + 1] | p32[2 * (lane + 32) + 1]) == 0u;
    return __ballot_sync(0xFFFFFFFFu, all0) == 0xFFFFFFFFu;
}
__device__ __forceinline__ long long load_idx(const void* p, int is64, long long j) {
    if (is64) return ((const long long*)p)[j];
    return (long long)((const int*)p)[j];
}

__device__ __forceinline__ void hash_add(unsigned key) {
    unsigned idx = (key * 2654435761u) & HMASK;
    for (;;) {
        unsigned cur = g_hk[idx];
        if (cur == key + 1u) { atomicAdd(&g_hc[idx], 1u); return; }
        if (cur == 0u) {
            unsigned old = atomicCAS(&g_hk[idx], 0u, key + 1u);
            if (old == 0u || old == key + 1u) { atomicAdd(&g_hc[idx], 1u); return; }
        }
        idx = (idx + 1u) & HMASK;
    }
}
__device__ __forceinline__ unsigned hash_get(unsigned key) {
    unsigned idx = (key * 2654435761u) & HMASK;
    for (;;) {
        unsigned cur = g_hk[idx];
        if (cur == 0u) return 0u;
        if (cur == key + 1u) return g_hc[idx];
        idx = (idx + 1u) & HMASK;
    }
}

// ---------------------------------------------------------------------------
// 0) Flag target nodes (idempotent across replays)
// ---------------------------------------------------------------------------
__global__ void flag_kernel(const void* __restrict__ tar) {
    int is64 = detect64(tar);
    int t = blockIdx.x * blockDim.x + threadIdx.x;
    if (t >= 2 * N_PAIRS) return;
    long long n = load_idx(tar, is64, t);
    g_F[n] = 1;
}

// ---------------------------------------------------------------------------
// 1) Scatter: one thread per DIRECTED edge; atomic only into TARGET rows.
// ---------------------------------------------------------------------------
__global__ void scatter_kernel(const void* __restrict__ ei) {
    int is64 = detect64(ei);
    int t = blockIdx.x * blockDim.x + threadIdx.x;
    if (t >= 2 * N_EDGES) return;

    int e   = (t < N_EDGES) ? t : t - N_EDGES;
    int rev = (t >= N_EDGES);

    long long a = load_idx(ei, is64, e);
    long long b = load_idx(ei, is64, (long long)N_EDGES + e);
    long long s = rev ? b : a;
    long long d = rev ? a : b;

    if (!g_F[s]) return;

    unsigned bd = 1u << (d & 31);
    unsigned old = atomicOr(&g_B[(size_t)s * ROW_WB + (size_t)(d >> 5)], bd);
    if (old & bd) hash_add((unsigned)(s * 16384 + d));
}

// ---------------------------------------------------------------------------
// 2) Pairs: intersect rows, build xs, init out[b] = b2[0]
// ---------------------------------------------------------------------------
__global__ void pairs_kernel(const void* __restrict__ tar,
                             const float* __restrict__ x,
                             const float* __restrict__ b2,
                             float* __restrict__ out) {
    __shared__ int   s_n[512];
    __shared__ float s_w[512];
    __shared__ int   s_cnt;

    int is64 = detect64(tar);
    int b   = blockIdx.x;
    int tid = threadIdx.x;
    if (tid == 0) {
        s_cnt = 0;
        out[b] = b2[0];
    }
    __syncthreads();

    long long ti = load_idx(tar, is64, b);
    long long tj = load_idx(tar, is64, (long long)N_PAIRS + b);

    if (tid < ROW_B4) {
        const uint4* rowi = reinterpret_cast<const uint4*>(&g_B[(size_t)ti * ROW_WB]);
        const uint4* rowj = reinterpret_cast<const uint4*>(&g_B[(size_t)tj * ROW_WB]);
        uint4 a = rowi[tid];
        uint4 q = rowj[tid];
        unsigned int m4[4] = {a.x & q.x, a.y & q.y, a.z & q.z, a.w & q.w};
#pragma unroll
        for (int w = 0; w < 4; w++) {
            unsigned int m = m4[w];
            while (m) {
                int bit = __ffs(m) - 1;
                int n = tid * 128 + w * 32 + bit;
                unsigned ua = 1u + hash_get((unsigned)(ti * 16384 + n));
                unsigned ub = 1u + hash_get((unsigned)(tj * 16384 + n));
                int idx = atomicAdd(&s_cnt, 1);
                if (idx < 512) {
                    s_n[idx] = n;
                    s_w[idx] = (float)(ua * ub);
                }
                m &= m - 1;
            }
        }
    }
    __syncthreads();

    int cnt = s_cnt < 512 ? s_cnt : 512;

    float xi = x[(size_t)ti * IN_CH + tid];
    float xj = x[(size_t)tj * IN_CH + tid];

    float acc = 0.f;
    for (int e = 0; e < cnt; e++)
        acc = fmaf(s_w[e], x[(size_t)s_n[e] * IN_CH + tid], acc);

    g_XS[(size_t)b * (2 * IN_CH) + tid]         = xi * xj;
    g_XS[(size_t)b * (2 * IN_CH) + IN_CH + tid] = acc;
}

// ---------------------------------------------------------------------------
// 3) Fused GEMM v2 hot loop, DOUBLE-BUFFERED smem (1 sync/tile, 8 total).
//    + atomicAdd epilogue + clear tail. Dynamic smem 50176 B.
// ---------------------------------------------------------------------------
#define BM 128
#define BN 64
#define BK 32
#define KTOT (2 * IN_CH)
#define NTILES (KTOT / BK)           // 8
#define XP (BM + 4)                  // 132 floats per k-row
#define STAGE_X (BK * XP)            // 4224 floats
#define STAGE_W (BK * BN)            // 2048 floats
#define STAGE_F (STAGE_X + STAGE_W)  // 6272 floats per stage
#define SMEM_MLP (2 * STAGE_F * 4)   // 50176 bytes

__device__ __forceinline__ unsigned long long fma2(
    unsigned long long a, unsigned long long b, unsigned long long c) {
    unsigned long long d;
    asm("fma.rn.f32x2 %0, %1, %2, %3;" : "=l"(d) : "l"(a), "l"(b), "l"(c));
    return d;
}
__device__ __forceinline__ unsigned long long dup2(float w) {
    unsigned long long r;
    asm("mov.b64 %0, {%1, %1};" : "=l"(r) : "r"(__float_as_uint(w)));
    return r;
}

__global__ __launch_bounds__(256, 1)
void mlp_kernel(const float* __restrict__ W1, const float* __restrict__ b1,
                const float* __restrict__ W2, float* __restrict__ out) {
    extern __shared__ __align__(16) float smf[];
    // stage s: x at smf[s*STAGE_F], w at smf[s*STAGE_F + STAGE_X]
    float* s_red = smf;   // aliases stage 0 (safe; see epilogue comment)

    int tid = threadIdx.x;
    int tx  = tid & 15;
    int ty  = tid >> 4;
    int b0  = (blockIdx.x & 15) * BM;
    int h0  = (blockIdx.x >> 4) * BN;

    float4 xr[4];
    float4 wr[2];

    // helper lambdas (inlined)
    auto load_tile = [&](int t) {
#pragma unroll
        for (int l = 0; l < 4; l++) {
            int fi = tid + l * 256;
            int p  = fi >> 3;
            int kc = fi & 7;
            xr[l] = *reinterpret_cast<const float4*>(
                &g_XS[(size_t)(b0 + p) * KTOT + t * BK + kc * 4]);
        }
#pragma unroll
        for (int l = 0; l < 2; l++) {
            int fi = tid + l * 256;
            int kk = fi >> 4;
            int cc = (fi & 15) * 4;
            wr[l] = *reinterpret_cast<const float4*>(
                &W1[(size_t)(t * BK + kk) * HIDDEN + h0 + cc]);
        }
    };
    auto store_tile = [&](int s) {
        float* sx = smf + s * STAGE_F;
        float* sw = smf + s * STAGE_F + STAGE_X;
#pragma unroll
        for (int l = 0; l < 4; l++) {
            int fi = tid + l * 256;
            int p  = fi >> 3;
            int kc = fi & 7;
            sx[(kc * 4 + 0) * XP + p] = xr[l].x;
            sx[(kc * 4 + 1) * XP + p] = xr[l].y;
            sx[(kc * 4 + 2) * XP + p] = xr[l].z;
            sx[(kc * 4 + 3) * XP + p] = xr[l].w;
        }
#pragma unroll
        for (int l = 0; l < 2; l++) {
            int fi = tid + l * 256;
            int kk = fi >> 4;
            int cc = (fi & 15) * 4;
            *reinterpret_cast<float4*>(&sw[kk * BN + cc]) = wr[l];
        }
    };

    unsigned long long acc2[4][4];
#pragma unroll
    for (int i = 0; i < 4; i++)
#pragma unroll
        for (int j = 0; j < 4; j++) acc2[i][j] = 0ull;

    // prologue: tile 0 -> smem stage 0; tile 1 -> regs
    load_tile(0);
    store_tile(0);
    load_tile(1);

    for (int t = 0; t < NTILES; t++) {
        __syncthreads();   // stage (t&1) fully stored; stage ((t+1)&1) free to overwrite

        const float* sx = smf + (t & 1) * STAGE_F;
        const float* sw = smf + (t & 1) * STAGE_F + STAGE_X;

#pragma unroll 8
        for (int k = 0; k < BK; k++) {
            float4 wv = *reinterpret_cast<const float4*>(&sw[k * BN + tx * 4]);
            unsigned long long wd[4];
            wd[0] = dup2(wv.x); wd[1] = dup2(wv.y);
            wd[2] = dup2(wv.z); wd[3] = dup2(wv.w);
            ulonglong2 xa = *reinterpret_cast<const ulonglong2*>(&sx[k * XP + ty * 8]);
            ulonglong2 xb = *reinterpret_cast<const ulonglong2*>(&sx[k * XP + ty * 8 + 4]);
            unsigned long long xp[4] = {xa.x, xa.y, xb.x, xb.y};
#pragma unroll
            for (int pp = 0; pp < 4; pp++)
#pragma unroll
                for (int hh = 0; hh < 4; hh++)
                    acc2[pp][hh] = fma2(xp[pp], wd[hh], acc2[pp][hh]);
        }

        if (t + 1 < NTILES) {
            store_tile((t + 1) & 1);           // regs hold tile t+1
            if (t + 2 < NTILES) load_tile(t + 2);
        }
    }

    // epilogue: relu + W2 weighting, per-pair reduce over 16 tx lanes.
    // s_red aliases stage 0; last compute tile (t=7) read stage 1, and all
    // stage-0 reads finished before the t=7 top-sync -> safe to overwrite.
    float4 b1v = *reinterpret_cast<const float4*>(&b1[h0 + tx * 4]);
    float4 w2v = *reinterpret_cast<const float4*>(&W2[h0 + tx * 4]);
    float bb[4] = {b1v.x, b1v.y, b1v.z, b1v.w};
    float ww[4] = {w2v.x, w2v.y, w2v.z, w2v.w};

    float pval[8];
#pragma unroll
    for (int pp = 0; pp < 4; pp++) {
        float lo = 0.f, hi = 0.f;
#pragma unroll
        for (int hh = 0; hh < 4; hh++) {
            union { unsigned long long u; float2 f; } cv;
            cv.u = acc2[pp][hh];
            lo += fmaxf(cv.f.x + bb[hh], 0.f) * ww[hh];
            hi += fmaxf(cv.f.y + bb[hh], 0.f) * ww[hh];
        }
        pval[pp * 2 + 0] = lo;
        pval[pp * 2 + 1] = hi;
    }

#pragma unroll
    for (int q = 0; q < 8; q++)
        s_red[(ty * 8 + q) * 17 + tx] = pval[q];
    __syncthreads();

    if (tid < BM) {
        float s = 0.f;
#pragma unroll
        for (int t = 0; t < 16; t++) s += s_red[tid * 17 + t];
        atomicAdd(&out[b0 + tid], s);
    }

    // -------- clear tail: this block zeroes its 1/128 slice of bitmap + hash
    {
        uint4 z = make_uint4(0u, 0u, 0u, 0u);
        uint4* bp = reinterpret_cast<uint4*>(g_B);
        size_t start = (size_t)blockIdx.x * (BMP_U4 / 128);
        size_t end   = start + (BMP_U4 / 128);
        for (size_t w = start + tid; w < end; w += 256)
            bp[w] = z;

        int hs = blockIdx.x * (HSIZE / 4 / 128);
        if (tid < HSIZE / 4 / 128) {
            reinterpret_cast<uint4*>(g_hk)[hs + tid] = z;
            reinterpret_cast<uint4*>(g_hc)[hs + tid] = z;
        }
    }
}

// ---------------------------------------------------------------------------
// launch (single stream, serial, 4 kernels)
// ---------------------------------------------------------------------------
extern "C" void kernel_launch(void* const* d_in, const int* in_sizes, int n_in,
                              void* d_out, int out_size) {
    const float* x   = (const float*)d_in[0];
    const void*  ei  = d_in[1];
    const void*  tar = d_in[2];
    const float* W1  = (const float*)d_in[3];
    const float* b1  = (const float*)d_in[4];
    const float* W2  = (const float*)d_in[5];
    const float* b2  = (const float*)d_in[6];
    float*       out = (float*)d_out;

    (void)in_sizes; (void)n_in; (void)out_size;

    static bool attr_ok = []() {
        cudaFuncSetAttribute(mlp_kernel,
                             cudaFuncAttributeMaxDynamicSharedMemorySize, SMEM_MLP);
        return true;
    }();
    (void)attr_ok;

    flag_kernel<<<(2 * N_PAIRS + 255) / 256, 256>>>(tar);
    scatter_kernel<<<(2 * N_EDGES + 255) / 256, 256>>>(ei);
    pairs_kernel<<<N_PAIRS, 128>>>(tar, x, b2, out);
    mlp_kernel<<<128, 256, SMEM_MLP>>>(W1, b1, W2, out);
}